// round 5
// baseline (speedup 1.0000x reference)
#include <cuda_runtime.h>
#include <cuda_fp16.h>
#include <cstdint>

#define NUM_USERS 100000
#define NUM_ITEMS 50000
#define DIM 64
#define NUM_REL 5
#define MAX_EDGES 2000000

typedef unsigned long long ull;

__device__ __half g_Ti[(size_t)NUM_ITEMS * NUM_REL * DIM];  // 32 MB
__device__ __half g_uh[(size_t)NUM_USERS * DIM];            // 12.8 MB
__device__ float  g_bi[(size_t)NUM_ITEMS * 8];              // stride 8
__device__ int    g_idx64;
__device__ int    g_cnt[NUM_ITEMS];
__device__ int    g_base[NUM_ITEMS];
__device__ int    g_woff[NUM_ITEMS];
__device__ int    g_cursor;
__device__ int2   g_pairs[MAX_EDGES];                       // (user, orig_e) 16 MB

// ---------------------------------------------------------------------------
// f32x2 helpers (Blackwell packed fp32 pipe)
// ---------------------------------------------------------------------------
__device__ __forceinline__ void fma2(ull& d, ull a, ull b) {
    asm("fma.rn.f32x2 %0, %1, %2, %0;" : "+l"(d) : "l"(a), "l"(b));
}
__device__ __forceinline__ ull dup2(float v) {
    ull p; asm("mov.b64 %0, {%1, %1};" : "=l"(p) : "f"(v)); return p;
}
__device__ __forceinline__ ull pack2(float x, float y) {
    ull p; asm("mov.b64 %0, {%1, %2};" : "=l"(p) : "f"(x), "f"(y)); return p;
}
__device__ __forceinline__ float2 unpack2(ull p) {
    float2 r; asm("mov.b64 {%0, %1}, %2;" : "=f"(r.x), "=f"(r.y) : "l"(p)); return r;
}
__device__ __forceinline__ ull h2_to_f32x2(unsigned int h2) {
    float2 f = __half22float2(*(const __half2*)&h2);
    return pack2(f.x, f.y);
}

// ---------------------------------------------------------------------------
// prep: zero counters/cursor, detect index width, convert u -> fp16.
// ---------------------------------------------------------------------------
__global__ void prep_kernel(const float* __restrict__ uf,
                            const void* __restrict__ eu) {
    int gid = blockIdx.x * blockDim.x + threadIdx.x;
    if (gid == 0) {
        g_cursor = 0;
        const int* p = (const int*)eu;
        int is64 = 1;
        #pragma unroll
        for (int j = 1; j < 16; j += 2)
            if (p[j] != 0) is64 = 0;
        g_idx64 = is64;
    }
    if (gid < NUM_ITEMS) g_cnt[gid] = 0;
    size_t i = (size_t)gid;
    size_t n = (size_t)NUM_USERS * DIM / 2;
    if (i < n) {
        float2 v = ((const float2*)uf)[i];
        ((__half2*)g_uh)[i] = __floats2half2_rn(v.x, v.y);
    }
}

// ---------------------------------------------------------------------------
// count edges per item
// ---------------------------------------------------------------------------
__global__ void count_kernel(const void* __restrict__ edge_i, int E) {
    int e = blockIdx.x * blockDim.x + threadIdx.x;
    if (e >= E) return;
    int item = g_idx64 ? (int)__ldg((const long long*)edge_i + e)
                       : __ldg((const int*)edge_i + e);
    atomicAdd(&g_cnt[item], 1);
}

// ---------------------------------------------------------------------------
// bases: per-item bin start via block-aggregated atomic cursor.
// (Bin placement order is nondeterministic; results are order-independent.)
// ---------------------------------------------------------------------------
__global__ void bases_kernel() {
    __shared__ int wsum[8];
    __shared__ int bbase;
    int i = blockIdx.x * blockDim.x + threadIdx.x;
    int lane = threadIdx.x & 31;
    int wid  = threadIdx.x >> 5;
    int c = (i < NUM_ITEMS) ? g_cnt[i] : 0;

    // warp inclusive scan
    int incl = c;
    #pragma unroll
    for (int off = 1; off < 32; off <<= 1) {
        int t = __shfl_up_sync(0xffffffffu, incl, off);
        if (lane >= off) incl += t;
    }
    if (lane == 31) wsum[wid] = incl;
    __syncthreads();
    if (threadIdx.x == 0) {
        int s = 0;
        #pragma unroll
        for (int w = 0; w < 8; w++) { int t = wsum[w]; wsum[w] = s; s += t; }
        bbase = atomicAdd(&g_cursor, s);
    }
    __syncthreads();
    int base = bbase + wsum[wid] + (incl - c);
    if (i < NUM_ITEMS) { g_base[i] = base; g_woff[i] = base; }
}

// ---------------------------------------------------------------------------
// scatter: place (user, orig_e) into its item's bin
// ---------------------------------------------------------------------------
__global__ void scatter_kernel(const void* __restrict__ edge_u,
                               const void* __restrict__ edge_i, int E) {
    int e = blockIdx.x * blockDim.x + threadIdx.x;
    if (e >= E) return;
    int user, item;
    if (g_idx64) {
        user = (int)__ldg((const long long*)edge_u + e);
        item = (int)__ldg((const long long*)edge_i + e);
    } else {
        user = __ldg((const int*)edge_u + e);
        item = __ldg((const int*)edge_i + e);
    }
    int pos = atomicAdd(&g_woff[item], 1);
    g_pairs[pos] = make_int2(user, e);
}

// ---------------------------------------------------------------------------
// Precompute Ti (register-tiled GEMM, f32x2 FMA) + fused bi.
// TILE 32 items, 128 threads: thread (g=tid>>4, c=tid&15) owns 4 items x 4 cols.
// ---------------------------------------------------------------------------
#define TILE_ITEMS 32
__global__ __launch_bounds__(128, 7) void precompute_kernel(
        const float* __restrict__ ifeat,
        const float* __restrict__ W,
        const float* __restrict__ b) {
    __shared__ ull   As2[TILE_ITEMS * DIM];   // duplicated {a,a} pairs, 16 KB
    __shared__ float Ws[DIM * DIM];           // one relation's W, 16 KB

    int tid   = threadIdx.x;
    int item0 = blockIdx.x * TILE_ITEMS;
    int c = tid & 15;
    int g = tid >> 4;   // 0..7 -> items 4g..4g+3

    for (int idx = tid; idx < TILE_ITEMS * DIM; idx += 128) {
        int it = idx >> 6, d = idx & 63;
        int gi = item0 + it;
        if (gi >= NUM_ITEMS) gi = NUM_ITEMS - 1;
        As2[idx] = dup2(__ldg(ifeat + (size_t)gi * DIM + d));
    }
    __syncthreads();

    // fused bi: 160 (item, rel) dots over 128 threads
    for (int idx = tid; idx < TILE_ITEMS * NUM_REL; idx += 128) {
        int it = idx / NUM_REL;
        int r  = idx - it * NUM_REL;
        int gi = item0 + it;
        if (gi < NUM_ITEMS) {
            const float* brow = b + (size_t)r * DIM;
            float s = 0.0f;
            #pragma unroll 16
            for (int d = 0; d < DIM; d++) {
                float2 a = unpack2(As2[it * DIM + d]);
                s = fmaf(a.x, __ldg(brow + d), s);
            }
            g_bi[(size_t)gi * 8 + r] = s;
        }
    }

    for (int r = 0; r < NUM_REL; r++) {
        __syncthreads();
        for (int idx = tid; idx < DIM * DIM / 4; idx += 128)
            ((float4*)Ws)[idx] =
                __ldg((const float4*)(W + (size_t)r * DIM * DIM) + idx);
        __syncthreads();

        ull acc[4][2] = {};
        #pragma unroll 4
        for (int d = 0; d < DIM; d += 2) {
            ulonglong2 w0 = *(const ulonglong2*)(Ws + (d + 0) * DIM + c * 4);
            ulonglong2 w1 = *(const ulonglong2*)(Ws + (d + 1) * DIM + c * 4);
            #pragma unroll
            for (int i = 0; i < 4; i++) {
                ulonglong2 a = *(const ulonglong2*)(As2 + (g * 4 + i) * DIM + d);
                fma2(acc[i][0], a.x, w0.x);
                fma2(acc[i][1], a.x, w0.y);
                fma2(acc[i][0], a.y, w1.x);
                fma2(acc[i][1], a.y, w1.y);
            }
        }

        #pragma unroll
        for (int i = 0; i < 4; i++) {
            int gi = item0 + g * 4 + i;
            if (gi < NUM_ITEMS) {
                float2 p0 = unpack2(acc[i][0]);
                float2 p1 = unpack2(acc[i][1]);
                __half2 h0 = __floats2half2_rn(p0.x, p0.y);
                __half2 h1 = __floats2half2_rn(p1.x, p1.y);
                uint2 st;
                st.x = *(unsigned int*)&h0;
                st.y = *(unsigned int*)&h1;
                *(uint2*)(g_Ti + ((size_t)gi * NUM_REL + r) * DIM + c * 4) = st;
            }
        }
    }
}

// ---------------------------------------------------------------------------
// Binned edge kernel: one warp per item. Ti row + bi live in registers
// (pre-converted to f32x2); 4 edge slots x 8 lanes per warp.
// ---------------------------------------------------------------------------
__global__ __launch_bounds__(256) void edge_kernel(float* __restrict__ out) {
    int wid  = (blockIdx.x * blockDim.x + threadIdx.x) >> 5;
    int item = wid;
    if (item >= NUM_ITEMS) return;
    int cnt = g_cnt[item];
    if (cnt == 0) return;
    int base = g_base[item];

    int lane = threadIdx.x & 31;
    int sl   = lane & 7;
    int slot = lane >> 3;
    unsigned grpmask = 0xFFu << (slot * 8);

    // Preload Ti row -> registers as f32x2 pairs (lane owns elements 8sl..8sl+7)
    const uint4* trow = (const uint4*)g_Ti + (size_t)item * (NUM_REL * 8);
    ull tf[NUM_REL][4];
    #pragma unroll
    for (int r = 0; r < NUM_REL; r++) {
        uint4 tv = __ldg(trow + r * 8 + sl);
        tf[r][0] = h2_to_f32x2(tv.x);
        tf[r][1] = h2_to_f32x2(tv.y);
        tf[r][2] = h2_to_f32x2(tv.z);
        tf[r][3] = h2_to_f32x2(tv.w);
    }
    float bi_l = __ldg(g_bi + (size_t)item * 8 + sl);   // padded to 8

    for (int j = slot; j < cnt; j += 4) {
        int2 pr = __ldg(g_pairs + base + j);            // (user, orig_e)
        uint4 uv = __ldg((const uint4*)g_uh + (size_t)pr.x * 8 + sl);
        ull uf0 = h2_to_f32x2(uv.x);
        ull uf1 = h2_to_f32x2(uv.y);
        ull uf2 = h2_to_f32x2(uv.z);
        ull uf3 = h2_to_f32x2(uv.w);

        float s[NUM_REL];
        #pragma unroll
        for (int r = 0; r < NUM_REL; r++) {
            ull acc = 0;
            fma2(acc, tf[r][0], uf0);
            fma2(acc, tf[r][1], uf1);
            fma2(acc, tf[r][2], uf2);
            fma2(acc, tf[r][3], uf3);
            float2 p = unpack2(acc);
            s[r] = p.x + p.y;
        }

        #pragma unroll
        for (int off = 4; off > 0; off >>= 1) {
            #pragma unroll
            for (int r = 0; r < NUM_REL; r++)
                s[r] += __shfl_xor_sync(grpmask, s[r], off);
        }

        if (sl < NUM_REL) {
            float v = (sl == 0) ? s[0] : (sl == 1) ? s[1] : (sl == 2) ? s[2]
                    : (sl == 3) ? s[3] : s[4];
            out[(size_t)pr.y * NUM_REL + sl] = v + bi_l;
        }
    }
}

// ---------------------------------------------------------------------------
extern "C" void kernel_launch(void* const* d_in, const int* in_sizes, int n_in,
                              void* d_out, int out_size) {
    const float* uf  = (const float*)d_in[0];
    const float* itf = (const float*)d_in[1];
    const void*  eu  = d_in[2];
    const void*  ei  = d_in[3];
    const float* W   = (const float*)d_in[4];
    const float* b   = (const float*)d_in[5];
    int E = in_sizes[2];
    if (E > MAX_EDGES) E = MAX_EDGES;

    static int inited = 0;
    if (!inited) {
        cudaFuncSetAttribute(precompute_kernel,
                             cudaFuncAttributePreferredSharedMemoryCarveout, 100);
        inited = 1;
    }

    {
        size_t n = (size_t)NUM_USERS * DIM / 2;
        prep_kernel<<<(unsigned)((n + 255) / 256), 256>>>(uf, eu);
    }
    count_kernel<<<(E + 255) / 256, 256>>>(ei, E);
    bases_kernel<<<(NUM_ITEMS + 255) / 256, 256>>>();
    scatter_kernel<<<(E + 255) / 256, 256>>>(eu, ei, E);
    {
        int blocks = (NUM_ITEMS + TILE_ITEMS - 1) / TILE_ITEMS;
        precompute_kernel<<<blocks, 128>>>(itf, W, b);
    }
    {
        int warps = NUM_ITEMS;               // one warp per item
        int blocks = (warps + 7) / 8;        // 8 warps / 256-thread block
        edge_kernel<<<blocks, 256>>>((float*)d_out);
    }
}